// round 10
// baseline (speedup 1.0000x reference)
#include <cuda_runtime.h>
#include <cuda_bf16.h>
#include <cuda_fp16.h>
#include <math.h>
#include <stdint.h>

#define N_NODES 100000
#define NROWS_PAD 100096          // 782 * 128
#define N_EDGES 800000
#define LN_EPS 1e-5f
#define SCAN_B 256
#define NB_SCAN ((N_NODES + SCAN_B - 1) / SCAN_B)   // 391

// ================= scratch (device globals; no allocation allowed) =================
__device__ float g_h[(size_t)N_NODES * 160];      // node state fp32
__device__ __half g_AB[(size_t)NROWS_PAD * 320];  // message A|B fp16 (L2-resident)
__device__ float g_tw[N_NODES];                   // gate
__device__ float g_bias320[320];                  // [bm | 0]

// CSR (dst-grouped, built once per launch)
__device__ int g_deg[N_NODES];
__device__ int g_rowstart[N_NODES + 1];
__device__ int g_cursor[N_NODES];
__device__ int g_eid[N_EDGES];
__device__ int g_bsum[512];

// bf16 hi/lo pre-split GEMM A operands
__device__ __align__(16) __nv_bfloat16 g_ah[(size_t)NROWS_PAD * 128], g_al[(size_t)NROWS_PAD * 128];   // node_features
__device__ __align__(16) __nv_bfloat16 g_hh[(size_t)NROWS_PAD * 192], g_hl[(size_t)NROWS_PAD * 192];   // h (K=160 pad 192)
__device__ __align__(16) __nv_bfloat16 g_uh[(size_t)NROWS_PAD * 320], g_ul[(size_t)NROWS_PAD * 320];   // U=[h|msg]

// bf16 hi/lo split weights (zero-padded K)
__device__ __align__(16) __nv_bfloat16 g_weh[128 * 128], g_wel[128 * 128];   // encoder
__device__ __align__(16) __nv_bfloat16 g_wmh[320 * 192], g_wml[320 * 192];   // message
__device__ __align__(16) __nv_bfloat16 g_wuh[160 * 320], g_wul[160 * 320];   // update
__device__ __align__(16) __nv_bfloat16 g_woh[128 * 192], g_wol[128 * 192];   // output

// ================= helpers =================
__device__ __forceinline__ uint32_t smem_u32(const void* p) {
    uint32_t a;
    asm("{ .reg .u64 t; cvta.to.shared.u64 t, %1; cvt.u32.u64 %0, t; }" : "=r"(a) : "l"(p));
    return a;
}
#define SWZ128(o) ((o) ^ (((o) >> 3) & 0x70))

__device__ __forceinline__ void cpa16(uint32_t dst, const void* src) {
    asm volatile("cp.async.cg.shared.global [%0], [%1], 16;" :: "r"(dst), "l"(src));
}
#define CP_COMMIT() asm volatile("cp.async.commit_group;" ::: "memory")
#define CP_WAIT0()  asm volatile("cp.async.wait_group 0;" ::: "memory")

__device__ __forceinline__ void ldsm4(uint32_t* r, uint32_t addr) {
    asm volatile("ldmatrix.sync.aligned.m8n8.x4.shared.b16 {%0,%1,%2,%3}, [%4];"
        : "=r"(r[0]), "=r"(r[1]), "=r"(r[2]), "=r"(r[3]) : "r"(addr));
}
__device__ __forceinline__ void mma16816(float* d, const uint32_t* a, const uint32_t* b) {
    asm volatile("mma.sync.aligned.m16n8k16.row.col.f32.bf16.bf16.f32 "
        "{%0,%1,%2,%3},{%4,%5,%6,%7},{%8,%9},{%0,%1,%2,%3};"
        : "+f"(d[0]), "+f"(d[1]), "+f"(d[2]), "+f"(d[3])
        : "r"(a[0]), "r"(a[1]), "r"(a[2]), "r"(a[3]), "r"(b[0]), "r"(b[1]));
}
__device__ __forceinline__ void split2(float a, float b, uint32_t& hi, uint32_t& lo) {
    __nv_bfloat16 ha = __float2bfloat16(a), hb = __float2bfloat16(b);
    __nv_bfloat16 la = __float2bfloat16(a - __bfloat162float(ha));
    __nv_bfloat16 lb = __float2bfloat16(b - __bfloat162float(hb));
    hi = (uint32_t)__bfloat16_as_ushort(ha) | ((uint32_t)__bfloat16_as_ushort(hb) << 16);
    lo = (uint32_t)__bfloat16_as_ushort(la) | ((uint32_t)__bfloat16_as_ushort(lb) << 16);
}
__device__ __forceinline__ void st_split1(__nv_bfloat16* H, __nv_bfloat16* L, size_t idx, float v) {
    __nv_bfloat16 h = __float2bfloat16(v);
    H[idx] = h;
    L[idx] = __float2bfloat16(v - __bfloat162float(h));
}
__device__ __forceinline__ void st_split4(__nv_bfloat16* H, __nv_bfloat16* L, size_t idx, float4 v) {
    uint2 hp, lp;
    split2(v.x, v.y, hp.x, lp.x);
    split2(v.z, v.w, hp.y, lp.y);
    *(uint2*)(H + idx) = hp;
    *(uint2*)(L + idx) = lp;
}
__device__ __forceinline__ float wsum(float v) {
#pragma unroll
    for (int o = 16; o; o >>= 1) v += __shfl_xor_sync(0xffffffffu, v, o);
    return v;
}

// ================= tensor-core GEMM (mma.sync bf16x3 split), fused epilogues ======
template<int NT, int KPAD, int EPI>
__global__ __launch_bounds__(256, 2) void gemm_tc(
    const __nv_bfloat16* __restrict__ Xh, const __nv_bfloat16* __restrict__ Xl,
    const __nv_bfloat16* __restrict__ Wh, const __nv_bfloat16* __restrict__ Wl,
    const float* __restrict__ bias,
    float* __restrict__ Y, int ldy,
    const float* __restrict__ a0, const float* __restrict__ a1,
    const float* __restrict__ a2, const float* __restrict__ a3,
    const float* __restrict__ a4, const float* __restrict__ a5,
    const float* __restrict__ a6,
    float* __restrict__ w0)
{
    extern __shared__ __align__(16) char dsm[];
    char* base = (char*)((((uintptr_t)dsm) + 1023) & ~(uintptr_t)1023);
    const uint32_t sb = smem_u32(base);
    constexpr int A_HI = 0, A_LO = 16384, B_HI = 32768;
    constexpr int B_LO = 32768 + NT * 128;
    constexpr int NW = NT / 2;
    constexpr int NTILES = NW / 8;
    const int tid = threadIdx.x, wid = tid >> 5, lane = tid & 31;
    const int wm = wid & 3, wn = wid >> 2;
    const int bm0 = blockIdx.y * 128, n0 = blockIdx.x * NT;

    float acc[2][NTILES][4];
#pragma unroll
    for (int m = 0; m < 2; m++)
#pragma unroll
        for (int t = 0; t < NTILES; t++)
#pragma unroll
            for (int j = 0; j < 4; j++) acc[m][t][j] = 0.f;

    constexpr int NCHUNK = KPAD / 64;
    for (int ch = 0; ch < NCHUNK; ch++) {
        const int c0 = ch * 64;
#pragma unroll
        for (int s = tid; s < 128 * 8; s += 256) {
            int r = s >> 3, i = s & 7;
            uint32_t off = SWZ128((uint32_t)(r * 128 + i * 16));
            cpa16(sb + A_HI + off, Xh + (size_t)(bm0 + r) * KPAD + c0 + i * 8);
            cpa16(sb + A_LO + off, Xl + (size_t)(bm0 + r) * KPAD + c0 + i * 8);
        }
        for (int s = tid; s < NT * 8; s += 256) {
            int r = s >> 3, i = s & 7;
            uint32_t off = SWZ128((uint32_t)(r * 128 + i * 16));
            cpa16(sb + B_HI + off, Wh + (size_t)(n0 + r) * KPAD + c0 + i * 8);
            cpa16(sb + B_LO + off, Wl + (size_t)(n0 + r) * KPAD + c0 + i * 8);
        }
        CP_COMMIT();
        CP_WAIT0();
        __syncthreads();

#pragma unroll
        for (int ks = 0; ks < 4; ks++) {
            uint32_t ah[2][4], al[2][4];
            const int arow = wm * 32 + (lane & 15);
            const int akb = ks * 32 + ((lane >> 4) << 4);
            {
                uint32_t o0 = SWZ128((uint32_t)(arow * 128 + akb));
                ldsm4(ah[0], sb + A_HI + o0);
                ldsm4(al[0], sb + A_LO + o0);
                uint32_t o1 = SWZ128((uint32_t)((arow + 16) * 128 + akb));
                ldsm4(ah[1], sb + A_HI + o1);
                ldsm4(al[1], sb + A_LO + o1);
            }
            const int q = lane >> 3;
            const int browb = wn * NW + ((q >> 1) << 3) + (lane & 7);
            const int bkb = ks * 32 + (q & 1) * 16;
#pragma unroll
            for (int nt = 0; nt < NTILES; nt += 2) {
                uint32_t bo = SWZ128((uint32_t)((browb + nt * 8) * 128 + bkb));
                uint32_t bh4[4], bl4[4];
                ldsm4(bh4, sb + B_HI + bo);
                ldsm4(bl4, sb + B_LO + bo);
                mma16816(acc[0][nt], ah[0], bh4);
                mma16816(acc[0][nt], ah[0], bl4);
                mma16816(acc[0][nt], al[0], bh4);
                mma16816(acc[1][nt], ah[1], bh4);
                mma16816(acc[1][nt], ah[1], bl4);
                mma16816(acc[1][nt], al[1], bh4);
                mma16816(acc[0][nt + 1], ah[0], bh4 + 2);
                mma16816(acc[0][nt + 1], ah[0], bl4 + 2);
                mma16816(acc[0][nt + 1], al[0], bh4 + 2);
                mma16816(acc[1][nt + 1], ah[1], bh4 + 2);
                mma16816(acc[1][nt + 1], ah[1], bl4 + 2);
                mma16816(acc[1][nt + 1], al[1], bh4 + 2);
            }
        }
        __syncthreads();
    }

    float* Dsm = (float*)base;
#pragma unroll
    for (int mb = 0; mb < 2; mb++) {
        const int r0 = wm * 32 + mb * 16 + (lane >> 2);
        const int c0 = wn * NW + (lane & 3) * 2;
#pragma unroll
        for (int nt = 0; nt < NTILES; nt++) {
            *(float2*)&Dsm[r0 * NT + c0 + nt * 8] = make_float2(acc[mb][nt][0], acc[mb][nt][1]);
            *(float2*)&Dsm[(r0 + 8) * NT + c0 + nt * 8] = make_float2(acc[mb][nt][2], acc[mb][nt][3]);
        }
    }
    __syncthreads();

    constexpr int NJ = NT / 32;
    for (int rr = 0; rr < 16; rr++) {
        const int r = wid * 16 + rr;
        const int gr = bm0 + r;
        const bool rv = gr < N_NODES;
        float v[NJ];
#pragma unroll
        for (int j = 0; j < NJ; j++) {
            int c = lane + 32 * j;
            v[j] = Dsm[r * NT + c] + bias[(EPI == 0 ? n0 : 0) + c];
        }

        if (EPI == 0) {
            if (rv) {
#pragma unroll
                for (int j = 0; j < NJ; j++)
                    g_AB[(size_t)gr * 320 + n0 + lane + 32 * j] = __float2half(v[j]);
            }
        } else if (EPI == 1 || EPI == 2) {
            float s = 0.f, q = 0.f;
#pragma unroll
            for (int j = 0; j < NJ; j++) { s += v[j]; q += v[j] * v[j]; }
            float mean = wsum(s) * (1.f / NT);
            float var = wsum(q) * (1.f / NT) - mean * mean;
            float rstd = rsqrtf(var + LN_EPS);
            if (rv) {
                if (EPI == 1) {
#pragma unroll
                    for (int j = 0; j < NJ; j++) {
                        int c = lane + 32 * j;
                        float hv = fmaxf(0.f, (v[j] - mean) * rstd * a0[c] + a1[c]);
                        Y[(size_t)gr * ldy + c] = hv;
                        st_split1(g_hh, g_hl, (size_t)gr * 192 + c, hv);
                    }
                    float t0 = a2[gr];
                    float tv = t0 * a3[lane] + a4[lane];
                    float tm = wsum(tv) * (1.f / 32.f);
                    float td = tv - tm;
                    float tvar = wsum(td * td) * (1.f / 32.f);
                    float tr = rsqrtf(tvar + LN_EPS);
                    float to = fmaxf(0.f, td * tr * a5[lane] + a6[lane]);
                    Y[(size_t)gr * ldy + 128 + lane] = to;
                    st_split1(g_hh, g_hl, (size_t)gr * 192 + 128 + lane, to);
                    g_hh[(size_t)gr * 192 + 160 + lane] = __float2bfloat16(0.f);
                    g_hl[(size_t)gr * 192 + 160 + lane] = __float2bfloat16(0.f);
                } else {
                    float tw = a2[gr];
#pragma unroll
                    for (int j = 0; j < NJ; j++) {
                        int c = lane + 32 * j;
                        float hn = fmaxf(0.f, (v[j] - mean) * rstd * a0[c] + a1[c]);
                        float ho = w0[(size_t)gr * 160 + c];
                        float hv = tw * hn + (1.f - tw) * ho;
                        w0[(size_t)gr * 160 + c] = hv;
                        st_split1(g_hh, g_hl, (size_t)gr * 192 + c, hv);
                    }
                    g_hh[(size_t)gr * 192 + 160 + lane] = __float2bfloat16(0.f);
                    g_hl[(size_t)gr * 192 + 160 + lane] = __float2bfloat16(0.f);
                }
            }
        } else {  // EPI == 3
            float q = 0.f;
#pragma unroll
            for (int j = 0; j < NJ; j++) q += v[j] * v[j];
            float sc = 1.f / fmaxf(sqrtf(wsum(q)), 1e-12f);
            if (rv) {
#pragma unroll
                for (int j = 0; j < NJ; j++)
                    Y[(size_t)gr * ldy + lane + 32 * j] = v[j] * sc;
            }
        }
    }
}

// ================= weight / input split kernels =================
__global__ void split_w(const float* __restrict__ W, __nv_bfloat16* __restrict__ H,
                        __nv_bfloat16* __restrict__ L, int NR, int K, int KPAD) {
    int t = blockIdx.x * blockDim.x + threadIdx.x;
    if (t >= NR * KPAD) return;
    int r = t / KPAD, c = t - r * KPAD;
    float v = (c < K) ? W[r * K + c] : 0.f;
    __nv_bfloat16 h = __float2bfloat16(v);
    H[t] = h;
    L[t] = __float2bfloat16(v - __bfloat162float(h));
}
__global__ void split_msg(const float* __restrict__ wm, const float* __restrict__ bm) {
    int t = blockIdx.x * blockDim.x + threadIdx.x;
    if (t < 320 * 192) {
        int r = t / 192, c = t - r * 192;
        float v = 0.f;
        if (c < 160) v = (r < 160) ? wm[r * 320 + c] : wm[(r - 160) * 320 + 160 + c];
        __nv_bfloat16 h = __float2bfloat16(v);
        g_wmh[t] = h;
        g_wml[t] = __float2bfloat16(v - __bfloat162float(h));
    }
    if (t < 320) g_bias320[t] = (t < 160) ? bm[t] : 0.f;
}

// ================= CSR build =================
__global__ void zero_deg() {
    int i = blockIdx.x * blockDim.x + threadIdx.x;
    if (i < N_NODES) g_deg[i] = 0;
}
__global__ void degree_kernel(const int* __restrict__ ei) {
    int e = blockIdx.x * blockDim.x + threadIdx.x;
    if (e < N_EDGES) atomicAdd(&g_deg[ei[N_EDGES + e]], 1);
}
__global__ void scan1() {
    __shared__ int sm[SCAN_B];
    int tid = threadIdx.x;
    int i = blockIdx.x * SCAN_B + tid;
    int v = (i < N_NODES) ? g_deg[i] : 0;
    sm[tid] = v;
    __syncthreads();
    for (int off = 1; off < SCAN_B; off <<= 1) {
        int t = (tid >= off) ? sm[tid - off] : 0;
        __syncthreads();
        sm[tid] += t;
        __syncthreads();
    }
    if (i < N_NODES) g_rowstart[i] = sm[tid] - v;   // block-local exclusive
    if (tid == SCAN_B - 1) g_bsum[blockIdx.x] = sm[tid];
}
__global__ void scan2() {
    __shared__ int sm[512];
    int tid = threadIdx.x;
    int v = (tid < NB_SCAN) ? g_bsum[tid] : 0;
    sm[tid] = v;
    __syncthreads();
    for (int off = 1; off < 512; off <<= 1) {
        int t = (tid >= off) ? sm[tid - off] : 0;
        __syncthreads();
        sm[tid] += t;
        __syncthreads();
    }
    if (tid < NB_SCAN) g_bsum[tid] = sm[tid] - v;   // exclusive
}
__global__ void scan3() {
    int i = blockIdx.x * blockDim.x + threadIdx.x;
    if (i < N_NODES) {
        int r = g_rowstart[i] + g_bsum[i / SCAN_B];
        g_rowstart[i] = r;
        g_cursor[i] = r;
    }
    if (i == 0) g_rowstart[N_NODES] = N_EDGES;
}
__global__ void scatter_eid(const int* __restrict__ ei) {
    int e = blockIdx.x * blockDim.x + threadIdx.x;
    if (e < N_EDGES) {
        int d = ei[N_EDGES + e];
        int pos = atomicAdd(&g_cursor[d], 1);
        g_eid[pos] = e;
    }
}

// ================= edge CSR consumer: per-dst warp, fused messages + node1 ========
__global__ __launch_bounds__(256) void edge_csr(
    const int* __restrict__ ei, const float* __restrict__ ew,
    const float* __restrict__ gmv, const float* __restrict__ bemv,
    const float* __restrict__ wgv, const float* __restrict__ bgv)
{
    int n = (blockIdx.x * blockDim.x + threadIdx.x) >> 5;
    int lane = threadIdx.x & 31;
    if (n >= N_NODES) return;
    const bool act = lane < 20;

    float bH[8], gv[8], bv[8];
#pragma unroll
    for (int k = 0; k < 8; k++) { bH[k] = 0.f; gv[k] = 0.f; bv[k] = 0.f; }
    if (act) {
        uint4 dvu = *(const uint4*)(g_AB + (size_t)n * 320 + 160 + lane * 8);
        const __half2* dh = (const __half2*)&dvu;
#pragma unroll
        for (int k = 0; k < 4; k++) {
            float2 t = __half22float2(dh[k]);
            bH[2 * k] = t.x; bH[2 * k + 1] = t.y;
        }
        float4 g0 = ((const float4*)gmv)[2 * lane], g1 = ((const float4*)gmv)[2 * lane + 1];
        float4 b0 = ((const float4*)bemv)[2 * lane], b1 = ((const float4*)bemv)[2 * lane + 1];
        gv[0] = g0.x; gv[1] = g0.y; gv[2] = g0.z; gv[3] = g0.w;
        gv[4] = g1.x; gv[5] = g1.y; gv[6] = g1.z; gv[7] = g1.w;
        bv[0] = b0.x; bv[1] = b0.y; bv[2] = b0.z; bv[3] = b0.w;
        bv[4] = b1.x; bv[5] = b1.y; bv[6] = b1.z; bv[7] = b1.w;
    }

    float acc[8];
#pragma unroll
    for (int k = 0; k < 8; k++) acc[k] = 0.f;

    const int s0 = g_rowstart[n], s1 = g_rowstart[n + 1];
    for (int p = s0; p < s1; p++) {
        int e = __ldg(&g_eid[p]);
        int src = __ldg(&ei[e]);
        float w = __ldg(&ew[e]);
        float v[8];
#pragma unroll
        for (int k = 0; k < 8; k++) v[k] = 0.f;
        if (act) {
            uint4 sv = *(const uint4*)(g_AB + (size_t)src * 320 + lane * 8);
            const __half2* sh = (const __half2*)&sv;
#pragma unroll
            for (int k = 0; k < 4; k++) {
                float2 t = __half22float2(sh[k]);
                v[2 * k]     = t.x + bH[2 * k];
                v[2 * k + 1] = t.y + bH[2 * k + 1];
            }
        }
        float s = 0.f;
#pragma unroll
        for (int k = 0; k < 8; k++) s += v[k];
        float mean = wsum(s) * (1.0f / 160.0f);
        float q = 0.f;
        if (act) {
#pragma unroll
            for (int k = 0; k < 8; k++) q += (v[k] - mean) * (v[k] - mean);
        }
        float rstd = rsqrtf(wsum(q) * (1.0f / 160.0f) + LN_EPS);
        if (act) {
#pragma unroll
            for (int k = 0; k < 8; k++)
                acc[k] += fmaxf(0.f, (v[k] - mean) * rstd * gv[k] + bv[k]) * w;
        }
    }

    const int deg = s1 - s0;
    const float inv = (deg > 0) ? 1.f / ((float)deg + 1e-8f) : 0.f;

    // fused node1: U=[h|messages] bf16 split + gate tw
    float dotp = 0.f;
    if (act) {
        const int c0 = lane * 8;
        const size_t ub = (size_t)n * 320;
        float4 h0 = *(const float4*)(g_h + (size_t)n * 160 + c0);
        float4 h1 = *(const float4*)(g_h + (size_t)n * 160 + c0 + 4);
        st_split4(g_uh, g_ul, ub + c0, h0);
        st_split4(g_uh, g_ul, ub + c0 + 4, h1);
        float4 m0 = make_float4(acc[0] * inv, acc[1] * inv, acc[2] * inv, acc[3] * inv);
        float4 m1 = make_float4(acc[4] * inv, acc[5] * inv, acc[6] * inv, acc[7] * inv);
        st_split4(g_uh, g_ul, ub + 160 + c0, m0);
        st_split4(g_uh, g_ul, ub + 160 + c0 + 4, m1);
        float4 wg0 = ((const float4*)wgv)[2 * lane], wg1 = ((const float4*)wgv)[2 * lane + 1];
        dotp = h0.x * wg0.x + h0.y * wg0.y + h0.z * wg0.z + h0.w * wg0.w
             + h1.x * wg1.x + h1.y * wg1.y + h1.z * wg1.z + h1.w * wg1.w;
    }
    float tot = wsum(dotp);
    if (lane == 0) g_tw[n] = 1.f / (1.f + expf(-(tot + bgv[0])));
}

// ================= host orchestration =================
extern "C" void kernel_launch(void* const* d_in, const int* in_sizes, int n_in,
                              void* d_out, int out_size)
{
    const float* node_features = (const float*)d_in[0];
    const int*   edge_index    = (const int*)d_in[1];
    const float* edge_weights  = (const float*)d_in[2];
    const float* time_steps    = (const float*)d_in[3];
    const float* w_enc   = (const float*)d_in[4];
    const float* b_enc   = (const float*)d_in[5];
    const float* g_enc   = (const float*)d_in[6];
    const float* be_enc  = (const float*)d_in[7];
    const float* w_time  = (const float*)d_in[8];
    const float* b_time  = (const float*)d_in[9];
    const float* g_time  = (const float*)d_in[10];
    const float* be_time = (const float*)d_in[11];
    const float* wm  = (const float*)d_in[12];
    const float* bm  = (const float*)d_in[13];
    const float* gm  = (const float*)d_in[14];
    const float* bem = (const float*)d_in[15];
    const float* wu  = (const float*)d_in[16];
    const float* bu  = (const float*)d_in[17];
    const float* gu  = (const float*)d_in[18];
    const float* beu = (const float*)d_in[19];
    const float* wg  = (const float*)d_in[20];
    const float* bg  = (const float*)d_in[21];
    const float* w_out = (const float*)d_in[22];
    const float* b_out = (const float*)d_in[23];
    float* out = (float*)d_out;

    float *p_h, *p_tw, *p_b320;
    __nv_bfloat16 *p_ah, *p_al, *p_hh, *p_hl, *p_uh, *p_ul;
    __nv_bfloat16 *p_weh, *p_wel, *p_wmh, *p_wml, *p_wuh, *p_wul, *p_woh, *p_wol;
    cudaGetSymbolAddress((void**)&p_h, g_h);
    cudaGetSymbolAddress((void**)&p_tw, g_tw);
    cudaGetSymbolAddress((void**)&p_b320, g_bias320);
    cudaGetSymbolAddress((void**)&p_ah, g_ah);
    cudaGetSymbolAddress((void**)&p_al, g_al);
    cudaGetSymbolAddress((void**)&p_hh, g_hh);
    cudaGetSymbolAddress((void**)&p_hl, g_hl);
    cudaGetSymbolAddress((void**)&p_uh, g_uh);
    cudaGetSymbolAddress((void**)&p_ul, g_ul);
    cudaGetSymbolAddress((void**)&p_weh, g_weh);
    cudaGetSymbolAddress((void**)&p_wel, g_wel);
    cudaGetSymbolAddress((void**)&p_wmh, g_wmh);
    cudaGetSymbolAddress((void**)&p_wml, g_wml);
    cudaGetSymbolAddress((void**)&p_wuh, g_wuh);
    cudaGetSymbolAddress((void**)&p_wul, g_wul);
    cudaGetSymbolAddress((void**)&p_woh, g_woh);
    cudaGetSymbolAddress((void**)&p_wol, g_wol);

    const int GBM = (N_NODES + 127) / 128;                   // 782
    const int NODE_WARP_BLOCKS = (N_NODES * 32 + 255) / 256; // 12500

    const int SM160 = 128 * 160 * 4 + 1024;
    const int SM128 = 128 * 128 * 4 + 1024;
    cudaFuncSetAttribute(gemm_tc<128, 128, 1>, cudaFuncAttributeMaxDynamicSharedMemorySize, SM128);
    cudaFuncSetAttribute(gemm_tc<160, 192, 0>, cudaFuncAttributeMaxDynamicSharedMemorySize, SM160);
    cudaFuncSetAttribute(gemm_tc<160, 320, 2>, cudaFuncAttributeMaxDynamicSharedMemorySize, SM160);
    cudaFuncSetAttribute(gemm_tc<128, 192, 3>, cudaFuncAttributeMaxDynamicSharedMemorySize, SM128);

    // ---- build dst-CSR once (layer-invariant) ----
    zero_deg<<<(N_NODES + 255) / 256, 256>>>();
    degree_kernel<<<(N_EDGES + 255) / 256, 256>>>(edge_index);
    scan1<<<NB_SCAN, SCAN_B>>>();
    scan2<<<1, 512>>>();
    scan3<<<(N_NODES + 255) / 256, 256>>>();
    scatter_eid<<<(N_EDGES + 255) / 256, 256>>>(edge_index);

    // ---- encoder ----
    split_w<<<(N_NODES * 128 + 255) / 256, 256>>>(node_features, p_ah, p_al, N_NODES, 128, 128);
    split_w<<<(128 * 128 + 255) / 256, 256>>>(w_enc, p_weh, p_wel, 128, 128, 128);
    gemm_tc<128, 128, 1><<<dim3(1, GBM), 256, SM128>>>(
        p_ah, p_al, p_weh, p_wel, b_enc, p_h, 160,
        g_enc, be_enc, time_steps, w_time, b_time, g_time, be_time, nullptr);

    for (int l = 0; l < 2; l++) {
        split_msg<<<(320 * 192 + 255) / 256, 256>>>(wm + (size_t)l * 160 * 320, bm + l * 160);
        gemm_tc<160, 192, 0><<<dim3(2, GBM), 256, SM160>>>(
            p_hh, p_hl, p_wmh, p_wml, p_b320, nullptr, 0,
            nullptr, nullptr, nullptr, nullptr, nullptr, nullptr, nullptr, nullptr);
        edge_csr<<<NODE_WARP_BLOCKS, 256>>>(edge_index, edge_weights,
                                            gm + l * 160, bem + l * 160, wg + l * 160, bg + l);
        split_w<<<(160 * 320 + 255) / 256, 256>>>(wu + (size_t)l * 160 * 320, p_wuh, p_wul, 160, 320, 320);
        gemm_tc<160, 320, 2><<<dim3(1, GBM), 256, SM160>>>(
            p_uh, p_ul, p_wuh, p_wul, bu + l * 160, nullptr, 0,
            gu + l * 160, beu + l * 160, p_tw, nullptr, nullptr, nullptr, nullptr, p_h);
    }

    split_w<<<(128 * 192 + 255) / 256, 256>>>(w_out, p_woh, p_wol, 128, 160, 192);
    gemm_tc<128, 192, 3><<<dim3(1, GBM), 256, SM128>>>(
        p_hh, p_hl, p_woh, p_wol, b_out, out, 128,
        nullptr, nullptr, nullptr, nullptr, nullptr, nullptr, nullptr, nullptr);
}

// round 11
// speedup vs baseline: 1.0101x; 1.0101x over previous
#include <cuda_runtime.h>
#include <cuda_bf16.h>
#include <cuda_fp16.h>
#include <math.h>
#include <stdint.h>

#define N_NODES 100000
#define NROWS_PAD 100096          // 782 * 128
#define N_EDGES 800000
#define LN_EPS 1e-5f

// ================= scratch (device globals; no allocation allowed) =================
__device__ float g_h[(size_t)N_NODES * 160];      // node state fp32
__device__ __half g_AB[(size_t)NROWS_PAD * 320];  // message A|B fp16 (L2-resident)
__device__ float g_msum[(size_t)N_NODES * 160];   // scatter-add accumulator
__device__ float g_cnt[N_NODES];                  // in-degree
__device__ float g_tw[N_NODES];                   // gate
__device__ float g_bias320[320];                  // [bm | 0]

// bf16 hi/lo pre-split GEMM A operands
__device__ __align__(16) __nv_bfloat16 g_ah[(size_t)NROWS_PAD * 128], g_al[(size_t)NROWS_PAD * 128];   // node_features
__device__ __align__(16) __nv_bfloat16 g_hh[(size_t)NROWS_PAD * 192], g_hl[(size_t)NROWS_PAD * 192];   // h (K=160 pad 192)
__device__ __align__(16) __nv_bfloat16 g_uh[(size_t)NROWS_PAD * 320], g_ul[(size_t)NROWS_PAD * 320];   // U=[h|msg]

// bf16 hi/lo split weights (zero-padded K)
__device__ __align__(16) __nv_bfloat16 g_weh[128 * 128], g_wel[128 * 128];   // encoder
__device__ __align__(16) __nv_bfloat16 g_wmh[320 * 192], g_wml[320 * 192];   // message
__device__ __align__(16) __nv_bfloat16 g_wuh[160 * 320], g_wul[160 * 320];   // update
__device__ __align__(16) __nv_bfloat16 g_woh[128 * 192], g_wol[128 * 192];   // output

// ================= helpers =================
__device__ __forceinline__ uint32_t smem_u32(const void* p) {
    uint32_t a;
    asm("{ .reg .u64 t; cvta.to.shared.u64 t, %1; cvt.u32.u64 %0, t; }" : "=r"(a) : "l"(p));
    return a;
}
#define SWZ128(o) ((o) ^ (((o) >> 3) & 0x70))

__device__ __forceinline__ void cpa16(uint32_t dst, const void* src) {
    asm volatile("cp.async.cg.shared.global [%0], [%1], 16;" :: "r"(dst), "l"(src));
}
#define CP_COMMIT() asm volatile("cp.async.commit_group;" ::: "memory")
#define CP_WAIT0()  asm volatile("cp.async.wait_group 0;" ::: "memory")
#define CP_WAIT1()  asm volatile("cp.async.wait_group 1;" ::: "memory")

__device__ __forceinline__ void ldsm4(uint32_t* r, uint32_t addr) {
    asm volatile("ldmatrix.sync.aligned.m8n8.x4.shared.b16 {%0,%1,%2,%3}, [%4];"
        : "=r"(r[0]), "=r"(r[1]), "=r"(r[2]), "=r"(r[3]) : "r"(addr));
}
__device__ __forceinline__ void mma16816(float* d, const uint32_t* a, const uint32_t* b) {
    asm volatile("mma.sync.aligned.m16n8k16.row.col.f32.bf16.bf16.f32 "
        "{%0,%1,%2,%3},{%4,%5,%6,%7},{%8,%9},{%0,%1,%2,%3};"
        : "+f"(d[0]), "+f"(d[1]), "+f"(d[2]), "+f"(d[3])
        : "r"(a[0]), "r"(a[1]), "r"(a[2]), "r"(a[3]), "r"(b[0]), "r"(b[1]));
}
__device__ __forceinline__ void split2(float a, float b, uint32_t& hi, uint32_t& lo) {
    __nv_bfloat16 ha = __float2bfloat16(a), hb = __float2bfloat16(b);
    __nv_bfloat16 la = __float2bfloat16(a - __bfloat162float(ha));
    __nv_bfloat16 lb = __float2bfloat16(b - __bfloat162float(hb));
    hi = (uint32_t)__bfloat16_as_ushort(ha) | ((uint32_t)__bfloat16_as_ushort(hb) << 16);
    lo = (uint32_t)__bfloat16_as_ushort(la) | ((uint32_t)__bfloat16_as_ushort(lb) << 16);
}
__device__ __forceinline__ void st_split1(__nv_bfloat16* H, __nv_bfloat16* L, size_t idx, float v) {
    __nv_bfloat16 h = __float2bfloat16(v);
    H[idx] = h;
    L[idx] = __float2bfloat16(v - __bfloat162float(h));
}
__device__ __forceinline__ void st_split4(__nv_bfloat16* H, __nv_bfloat16* L, size_t idx, float4 v) {
    uint2 hp, lp;
    split2(v.x, v.y, hp.x, lp.x);
    split2(v.z, v.w, hp.y, lp.y);
    *(uint2*)(H + idx) = hp;
    *(uint2*)(L + idx) = lp;
}
__device__ __forceinline__ float wsum(float v) {
#pragma unroll
    for (int o = 16; o; o >>= 1) v += __shfl_xor_sync(0xffffffffu, v, o);
    return v;
}
__device__ __forceinline__ void red4(float* p, float4 v) {
    asm volatile("red.global.add.v4.f32 [%0], {%1,%2,%3,%4};"
                 :: "l"(p), "f"(v.x), "f"(v.y), "f"(v.z), "f"(v.w) : "memory");
}

// ================= tensor-core GEMM: double-buffered 32-col chunks ================
// SMEM row layout per buffer: 128 bytes/row = [hi 64B | lo 64B] for a 32-col chunk.
// EPI: 0 msg precompute -> g_AB fp16; 1 encoder LN+relu+time+split; 2 update LN+relu+
//      gate blend+split; 3 output bias+L2 row-normalize
template<int NT, int KPAD, int EPI>
__global__ __launch_bounds__(256, 2) void gemm_tc(
    const __nv_bfloat16* __restrict__ Xh, const __nv_bfloat16* __restrict__ Xl,
    const __nv_bfloat16* __restrict__ Wh, const __nv_bfloat16* __restrict__ Wl,
    const float* __restrict__ bias,
    float* __restrict__ Y, int ldy,
    const float* __restrict__ a0, const float* __restrict__ a1,
    const float* __restrict__ a2, const float* __restrict__ a3,
    const float* __restrict__ a4, const float* __restrict__ a5,
    const float* __restrict__ a6,
    float* __restrict__ w0)
{
    extern __shared__ __align__(16) char dsm[];
    char* base = (char*)((((uintptr_t)dsm) + 1023) & ~(uintptr_t)1023);
    const uint32_t sb = smem_u32(base);
    constexpr int A0 = 0, A1 = 16384, B0 = 32768, B1 = 32768 + NT * 128;
    constexpr int NW = NT / 2;
    constexpr int NTILES = NW / 8;
    const int tid = threadIdx.x, wid = tid >> 5, lane = tid & 31;
    const int wm = wid & 3, wn = wid >> 2;
    const int bm0 = blockIdx.y * 128, n0 = blockIdx.x * NT;

    float acc[2][NTILES][4];
#pragma unroll
    for (int m = 0; m < 2; m++)
#pragma unroll
        for (int t = 0; t < NTILES; t++)
#pragma unroll
            for (int j = 0; j < 4; j++) acc[m][t][j] = 0.f;

    auto load_chunk = [&](int ch, int buf) {
        const int c0 = ch * 32;
        const uint32_t abase = sb + (buf ? A1 : A0);
        const uint32_t bbase = sb + (buf ? B1 : B0);
#pragma unroll
        for (int s = tid; s < 128 * 8; s += 256) {
            int r = s >> 3, i = s & 7;
            uint32_t off = SWZ128((uint32_t)(r * 128 + i * 16));
            const __nv_bfloat16* src = (i < 4)
                ? Xh + (size_t)(bm0 + r) * KPAD + c0 + i * 8
                : Xl + (size_t)(bm0 + r) * KPAD + c0 + (i - 4) * 8;
            cpa16(abase + off, src);
        }
        for (int s = tid; s < NT * 8; s += 256) {
            int r = s >> 3, i = s & 7;
            uint32_t off = SWZ128((uint32_t)(r * 128 + i * 16));
            const __nv_bfloat16* src = (i < 4)
                ? Wh + (size_t)(n0 + r) * KPAD + c0 + i * 8
                : Wl + (size_t)(n0 + r) * KPAD + c0 + (i - 4) * 8;
            cpa16(bbase + off, src);
        }
    };

    auto compute_chunk = [&](int buf) {
        const uint32_t abase = sb + (buf ? A1 : A0);
        const uint32_t bbase = sb + (buf ? B1 : B0);
#pragma unroll
        for (int ks = 0; ks < 2; ks++) {
            uint32_t ah[2][4], al[2][4];
            const int arow = wm * 32 + (lane & 15);
            const int akb = ks * 32 + ((lane >> 4) << 4);
            ldsm4(ah[0], abase + SWZ128((uint32_t)(arow * 128 + akb)));
            ldsm4(al[0], abase + SWZ128((uint32_t)(arow * 128 + 64 + akb)));
            ldsm4(ah[1], abase + SWZ128((uint32_t)((arow + 16) * 128 + akb)));
            ldsm4(al[1], abase + SWZ128((uint32_t)((arow + 16) * 128 + 64 + akb)));
            const int q = lane >> 3;
            const int browb = wn * NW + ((q >> 1) << 3) + (lane & 7);
            const int bkb = ks * 32 + (q & 1) * 16;
#pragma unroll
            for (int nt = 0; nt < NTILES; nt += 2) {
                uint32_t bh4[4], bl4[4];
                ldsm4(bh4, bbase + SWZ128((uint32_t)((browb + nt * 8) * 128 + bkb)));
                ldsm4(bl4, bbase + SWZ128((uint32_t)((browb + nt * 8) * 128 + 64 + bkb)));
                mma16816(acc[0][nt], ah[0], bh4);
                mma16816(acc[0][nt], ah[0], bl4);
                mma16816(acc[0][nt], al[0], bh4);
                mma16816(acc[1][nt], ah[1], bh4);
                mma16816(acc[1][nt], ah[1], bl4);
                mma16816(acc[1][nt], al[1], bh4);
                mma16816(acc[0][nt + 1], ah[0], bh4 + 2);
                mma16816(acc[0][nt + 1], ah[0], bl4 + 2);
                mma16816(acc[0][nt + 1], al[0], bh4 + 2);
                mma16816(acc[1][nt + 1], ah[1], bh4 + 2);
                mma16816(acc[1][nt + 1], ah[1], bl4 + 2);
                mma16816(acc[1][nt + 1], al[1], bh4 + 2);
            }
        }
    };

    constexpr int NC = KPAD / 32;
    load_chunk(0, 0);
    CP_COMMIT();
#pragma unroll 1
    for (int ch = 0; ch < NC; ch++) {
        if (ch + 1 < NC) {
            load_chunk(ch + 1, (ch + 1) & 1);
            CP_COMMIT();
            CP_WAIT1();
        } else {
            CP_WAIT0();
        }
        __syncthreads();
        compute_chunk(ch & 1);
        __syncthreads();
    }

    // ---------------- stage D in SMEM (reuse buffers), row-wise epilogue ----------
    float* Dsm = (float*)base;   // [128][NT]
#pragma unroll
    for (int mb = 0; mb < 2; mb++) {
        const int r0 = wm * 32 + mb * 16 + (lane >> 2);
        const int c0 = wn * NW + (lane & 3) * 2;
#pragma unroll
        for (int nt = 0; nt < NTILES; nt++) {
            *(float2*)&Dsm[r0 * NT + c0 + nt * 8] = make_float2(acc[mb][nt][0], acc[mb][nt][1]);
            *(float2*)&Dsm[(r0 + 8) * NT + c0 + nt * 8] = make_float2(acc[mb][nt][2], acc[mb][nt][3]);
        }
    }
    __syncthreads();

    constexpr int NJ = NT / 32;
    for (int rr = 0; rr < 16; rr++) {
        const int r = wid * 16 + rr;
        const int gr = bm0 + r;
        const bool rv = gr < N_NODES;
        float v[NJ];
#pragma unroll
        for (int j = 0; j < NJ; j++) {
            int c = lane + 32 * j;
            v[j] = Dsm[r * NT + c] + bias[(EPI == 0 ? n0 : 0) + c];
        }

        if (EPI == 0) {
            if (rv) {
#pragma unroll
                for (int j = 0; j < NJ; j++)
                    g_AB[(size_t)gr * 320 + n0 + lane + 32 * j] = __float2half(v[j]);
            }
        } else if (EPI == 1 || EPI == 2) {
            float s = 0.f, q = 0.f;
#pragma unroll
            for (int j = 0; j < NJ; j++) { s += v[j]; q += v[j] * v[j]; }
            float mean = wsum(s) * (1.f / NT);
            float var = wsum(q) * (1.f / NT) - mean * mean;
            float rstd = rsqrtf(var + LN_EPS);
            if (rv) {
                if (EPI == 1) {
#pragma unroll
                    for (int j = 0; j < NJ; j++) {
                        int c = lane + 32 * j;
                        float hv = fmaxf(0.f, (v[j] - mean) * rstd * a0[c] + a1[c]);
                        Y[(size_t)gr * ldy + c] = hv;
                        st_split1(g_hh, g_hl, (size_t)gr * 192 + c, hv);
                    }
                    float t0 = a2[gr];
                    float tv = t0 * a3[lane] + a4[lane];
                    float tm = wsum(tv) * (1.f / 32.f);
                    float td = tv - tm;
                    float tvar = wsum(td * td) * (1.f / 32.f);
                    float tr = rsqrtf(tvar + LN_EPS);
                    float to = fmaxf(0.f, td * tr * a5[lane] + a6[lane]);
                    Y[(size_t)gr * ldy + 128 + lane] = to;
                    st_split1(g_hh, g_hl, (size_t)gr * 192 + 128 + lane, to);
                    g_hh[(size_t)gr * 192 + 160 + lane] = __float2bfloat16(0.f);
                    g_hl[(size_t)gr * 192 + 160 + lane] = __float2bfloat16(0.f);
                } else {
                    float tw = a2[gr];
#pragma unroll
                    for (int j = 0; j < NJ; j++) {
                        int c = lane + 32 * j;
                        float hn = fmaxf(0.f, (v[j] - mean) * rstd * a0[c] + a1[c]);
                        float ho = w0[(size_t)gr * 160 + c];
                        float hv = tw * hn + (1.f - tw) * ho;
                        w0[(size_t)gr * 160 + c] = hv;
                        st_split1(g_hh, g_hl, (size_t)gr * 192 + c, hv);
                    }
                    g_hh[(size_t)gr * 192 + 160 + lane] = __float2bfloat16(0.f);
                    g_hl[(size_t)gr * 192 + 160 + lane] = __float2bfloat16(0.f);
                }
            }
        } else {  // EPI == 3
            float q = 0.f;
#pragma unroll
            for (int j = 0; j < NJ; j++) q += v[j] * v[j];
            float sc = 1.f / fmaxf(sqrtf(wsum(q)), 1e-12f);
            if (rv) {
#pragma unroll
                for (int j = 0; j < NJ; j++)
                    Y[(size_t)gr * ldy + lane + 32 * j] = v[j] * sc;
            }
        }
    }
}

// ================= weight / input split kernels =================
__global__ void split_w(const float* __restrict__ W, __nv_bfloat16* __restrict__ H,
                        __nv_bfloat16* __restrict__ L, int NR, int K, int KPAD) {
    int t = blockIdx.x * blockDim.x + threadIdx.x;
    if (t >= NR * KPAD) return;
    int r = t / KPAD, c = t - r * KPAD;
    float v = (c < K) ? W[r * K + c] : 0.f;
    __nv_bfloat16 h = __float2bfloat16(v);
    H[t] = h;
    L[t] = __float2bfloat16(v - __bfloat162float(h));
}
__global__ void split_msg(const float* __restrict__ wm, const float* __restrict__ bm) {
    int t = blockIdx.x * blockDim.x + threadIdx.x;
    if (t < 320 * 192) {
        int r = t / 192, c = t - r * 192;
        float v = 0.f;
        if (c < 160) v = (r < 160) ? wm[r * 320 + c] : wm[(r - 160) * 320 + 160 + c];
        __nv_bfloat16 h = __float2bfloat16(v);
        g_wmh[t] = h;
        g_wml[t] = __float2bfloat16(v - __bfloat162float(h));
    }
    if (t < 320) g_bias320[t] = (t < 160) ? bm[t] : 0.f;
}

// ================= zero / degree =================
__global__ void zero_cnt() {
    int i = blockIdx.x * blockDim.x + threadIdx.x;
    if (i < N_NODES) g_cnt[i] = 0.f;
}
__global__ void zero_msum() {
    int i = blockIdx.x * blockDim.x + threadIdx.x;
    int st = gridDim.x * blockDim.x;
    float4* p = (float4*)g_msum;
    const int n4 = N_NODES * 40;
    for (int k = i; k < n4; k += st) p[k] = make_float4(0.f, 0.f, 0.f, 0.f);
}
__global__ void degree_kernel(const int* __restrict__ ei) {
    int e = blockIdx.x * blockDim.x + threadIdx.x;
    if (e < N_EDGES) atomicAdd(&g_cnt[ei[N_EDGES + e]], 1.0f);
}

// ================= edge pass (fp16 gather, fp32 atomic scatter) =================
__global__ void edge_kernel(const int* __restrict__ ei, const float* __restrict__ ew,
                            const float* __restrict__ gmv, const float* __restrict__ bemv)
{
    int w = (blockIdx.x * blockDim.x + threadIdx.x) >> 5;
    int lane = threadIdx.x & 31;
    if (w >= N_EDGES) return;
    int src = ei[w];
    int dst = ei[N_EDGES + w];
    float ewt = ew[w];
    const bool act = lane < 20;

    float v[8];
#pragma unroll
    for (int k = 0; k < 8; k++) v[k] = 0.f;
    if (act) {
        uint4 sv = *(const uint4*)(g_AB + (size_t)src * 320 + lane * 8);
        uint4 dv = *(const uint4*)(g_AB + (size_t)dst * 320 + 160 + lane * 8);
        const __half2* sh = (const __half2*)&sv;
        const __half2* dh = (const __half2*)&dv;
#pragma unroll
        for (int k = 0; k < 4; k++) {
            float2 a = __half22float2(sh[k]);
            float2 b = __half22float2(dh[k]);
            v[2 * k + 0] = a.x + b.x;
            v[2 * k + 1] = a.y + b.y;
        }
    }

    float s = 0.f;
#pragma unroll
    for (int k = 0; k < 8; k++) s += v[k];
    float mean = wsum(s) * (1.0f / 160.0f);

    float q = 0.f;
    if (act) {
#pragma unroll
        for (int k = 0; k < 8; k++) q += (v[k] - mean) * (v[k] - mean);
    }
    float var = wsum(q) * (1.0f / 160.0f);
    float rstd = rsqrtf(var + LN_EPS);

    if (act) {
        const int c0 = lane * 8;
        float4 g0 = ((const float4*)gmv)[2 * lane];
        float4 g1 = ((const float4*)gmv)[2 * lane + 1];
        float4 b0 = ((const float4*)bemv)[2 * lane];
        float4 b1 = ((const float4*)bemv)[2 * lane + 1];
        float* basep = g_msum + (size_t)dst * 160 + c0;
        float4 o0, o1;
        o0.x = fmaxf(0.f, (v[0] - mean) * rstd * g0.x + b0.x) * ewt;
        o0.y = fmaxf(0.f, (v[1] - mean) * rstd * g0.y + b0.y) * ewt;
        o0.z = fmaxf(0.f, (v[2] - mean) * rstd * g0.z + b0.z) * ewt;
        o0.w = fmaxf(0.f, (v[3] - mean) * rstd * g0.w + b0.w) * ewt;
        o1.x = fmaxf(0.f, (v[4] - mean) * rstd * g1.x + b1.x) * ewt;
        o1.y = fmaxf(0.f, (v[5] - mean) * rstd * g1.y + b1.y) * ewt;
        o1.z = fmaxf(0.f, (v[6] - mean) * rstd * g1.z + b1.z) * ewt;
        o1.w = fmaxf(0.f, (v[7] - mean) * rstd * g1.w + b1.w) * ewt;
        red4(basep, o0);
        red4(basep + 4, o1);
    }
}

// ================= node pass 1: U=[h|messages] split to bf16, gate tw =============
__global__ void node1_kernel(const float* __restrict__ wgv, const float* __restrict__ bgv) {
    int n = (blockIdx.x * blockDim.x + threadIdx.x) >> 5;
    int lane = threadIdx.x & 31;
    if (n >= N_NODES) return;

    float c = g_cnt[n];
    float inv = (c > 0.f) ? 1.f / (c + 1e-8f) : 0.f;

    const float4* H = (const float4*)(g_h + (size_t)n * 160);
    const float4* Ms = (const float4*)(g_msum + (size_t)n * 160);
    const bool two = lane < 8;
    const size_t ub = (size_t)n * 320;

    float dotp = 0.f;
    {
        float4 h = H[lane];
        st_split4(g_uh, g_ul, ub + 4 * lane, h);
        float4 m = Ms[lane];
        float4 mm = make_float4(m.x * inv, m.y * inv, m.z * inv, m.w * inv);
        st_split4(g_uh, g_ul, ub + 160 + 4 * lane, mm);
        float4 wg = ((const float4*)wgv)[lane];
        dotp = h.x * wg.x + h.y * wg.y + h.z * wg.z + h.w * wg.w;
    }
    if (two) {
        float4 h = H[lane + 32];
        st_split4(g_uh, g_ul, ub + 128 + 4 * lane, h);
        float4 m = Ms[lane + 32];
        float4 mm = make_float4(m.x * inv, m.y * inv, m.z * inv, m.w * inv);
        st_split4(g_uh, g_ul, ub + 160 + 128 + 4 * lane, mm);
        float4 wg = ((const float4*)wgv)[lane + 32];
        dotp += h.x * wg.x + h.y * wg.y + h.z * wg.z + h.w * wg.w;
    }
    float tot = wsum(dotp);
    if (lane == 0) g_tw[n] = 1.f / (1.f + expf(-(tot + bgv[0])));
}

// ================= host orchestration =================
extern "C" void kernel_launch(void* const* d_in, const int* in_sizes, int n_in,
                              void* d_out, int out_size)
{
    const float* node_features = (const float*)d_in[0];
    const int*   edge_index    = (const int*)d_in[1];
    const float* edge_weights  = (const float*)d_in[2];
    const float* time_steps    = (const float*)d_in[3];
    const float* w_enc   = (const float*)d_in[4];
    const float* b_enc   = (const float*)d_in[5];
    const float* g_enc   = (const float*)d_in[6];
    const float* be_enc  = (const float*)d_in[7];
    const float* w_time  = (const float*)d_in[8];
    const float* b_time  = (const float*)d_in[9];
    const float* g_time  = (const float*)d_in[10];
    const float* be_time = (const float*)d_in[11];
    const float* wm  = (const float*)d_in[12];
    const float* bm  = (const float*)d_in[13];
    const float* gm  = (const float*)d_in[14];
    const float* bem = (const float*)d_in[15];
    const float* wu  = (const float*)d_in[16];
    const float* bu  = (const float*)d_in[17];
    const float* gu  = (const float*)d_in[18];
    const float* beu = (const float*)d_in[19];
    const float* wg  = (const float*)d_in[20];
    const float* bg  = (const float*)d_in[21];
    const float* w_out = (const float*)d_in[22];
    const float* b_out = (const float*)d_in[23];
    float* out = (float*)d_out;

    float *p_h, *p_tw, *p_b320;
    __nv_bfloat16 *p_ah, *p_al, *p_hh, *p_hl, *p_uh, *p_ul;
    __nv_bfloat16 *p_weh, *p_wel, *p_wmh, *p_wml, *p_wuh, *p_wul, *p_woh, *p_wol;
    cudaGetSymbolAddress((void**)&p_h, g_h);
    cudaGetSymbolAddress((void**)&p_tw, g_tw);
    cudaGetSymbolAddress((void**)&p_b320, g_bias320);
    cudaGetSymbolAddress((void**)&p_ah, g_ah);
    cudaGetSymbolAddress((void**)&p_al, g_al);
    cudaGetSymbolAddress((void**)&p_hh, g_hh);
    cudaGetSymbolAddress((void**)&p_hl, g_hl);
    cudaGetSymbolAddress((void**)&p_uh, g_uh);
    cudaGetSymbolAddress((void**)&p_ul, g_ul);
    cudaGetSymbolAddress((void**)&p_weh, g_weh);
    cudaGetSymbolAddress((void**)&p_wel, g_wel);
    cudaGetSymbolAddress((void**)&p_wmh, g_wmh);
    cudaGetSymbolAddress((void**)&p_wml, g_wml);
    cudaGetSymbolAddress((void**)&p_wuh, g_wuh);
    cudaGetSymbolAddress((void**)&p_wul, g_wul);
    cudaGetSymbolAddress((void**)&p_woh, g_woh);
    cudaGetSymbolAddress((void**)&p_wol, g_wol);

    const int GBM = (N_NODES + 127) / 128;                   // 782
    const int NODE_WARP_BLOCKS = (N_NODES * 32 + 255) / 256; // 12500
    const int EDGE_WARP_BLOCKS = (N_EDGES * 32 + 255) / 256; // 100000

    const int SM160 = 128 * 160 * 4 + 1024;   // 82944
    const int SM128 = 128 * 128 * 4 + 1024;   // 66560
    cudaFuncSetAttribute(gemm_tc<128, 128, 1>, cudaFuncAttributeMaxDynamicSharedMemorySize, SM128);
    cudaFuncSetAttribute(gemm_tc<160, 192, 0>, cudaFuncAttributeMaxDynamicSharedMemorySize, SM160);
    cudaFuncSetAttribute(gemm_tc<160, 320, 2>, cudaFuncAttributeMaxDynamicSharedMemorySize, SM160);
    cudaFuncSetAttribute(gemm_tc<128, 192, 3>, cudaFuncAttributeMaxDynamicSharedMemorySize, SM128);

    // degrees (constant across layers)
    zero_cnt<<<(N_NODES + 255) / 256, 256>>>();
    degree_kernel<<<(N_EDGES + 255) / 256, 256>>>(edge_index);

    // split inputs/weights for encoder
    split_w<<<(N_NODES * 128 + 255) / 256, 256>>>(node_features, p_ah, p_al, N_NODES, 128, 128);
    split_w<<<(128 * 128 + 255) / 256, 256>>>(w_enc, p_weh, p_wel, 128, 128, 128);
    gemm_tc<128, 128, 1><<<dim3(1, GBM), 256, SM128>>>(
        p_ah, p_al, p_weh, p_wel, b_enc, p_h, 160,
        g_enc, be_enc, time_steps, w_time, b_time, g_time, be_time, nullptr);

    for (int l = 0; l < 2; l++) {
        split_msg<<<(320 * 192 + 255) / 256, 256>>>(wm + (size_t)l * 160 * 320, bm + l * 160);
        gemm_tc<160, 192, 0><<<dim3(2, GBM), 256, SM160>>>(
            p_hh, p_hl, p_wmh, p_wml, p_b320, nullptr, 0,
            nullptr, nullptr, nullptr, nullptr, nullptr, nullptr, nullptr, nullptr);
        zero_msum<<<4096, 256>>>();
        edge_kernel<<<EDGE_WARP_BLOCKS, 256>>>(edge_index, edge_weights, gm + l * 160, bem + l * 160);
        node1_kernel<<<NODE_WARP_BLOCKS, 256>>>(wg + l * 160, bg + l);
        split_w<<<(160 * 320 + 255) / 256, 256>>>(wu + (size_t)l * 160 * 320, p_wuh, p_wul, 160, 320, 320);
        gemm_tc<160, 320, 2><<<dim3(1, GBM), 256, SM160>>>(
            p_uh, p_ul, p_wuh, p_wul, bu + l * 160, nullptr, 0,
            gu + l * 160, beu + l * 160, p_tw, nullptr, nullptr, nullptr, nullptr, p_h);
    }

    split_w<<<(128 * 192 + 255) / 256, 256>>>(w_out, p_woh, p_wol, 128, 160, 192);
    gemm_tc<128, 192, 3><<<dim3(1, GBM), 256, SM128>>>(
        p_hh, p_hl, p_woh, p_wol, b_out, out, 128,
        nullptr, nullptr, nullptr, nullptr, nullptr, nullptr, nullptr, nullptr);
}